// round 2
// baseline (speedup 1.0000x reference)
#include <cuda_runtime.h>

#define N_NODES 50000
#define EMB 35
#define DEG 32
#define PAD 40          // padded emb row: 160 B = exactly 5 L2 sectors

// ---------------- scratch (no allocs allowed) ----------------
__device__ float g_emb[N_NODES * PAD];   // transformed other-side embeddings (padded)
__device__ float g_sb[N_NODES];          // s_b = new_emb @ att[EMB:]
__device__ float g_m0[N_NODES * EMB];    // aggregated message (pos)
__device__ float g_m1[N_NODES * EMB];    // aggregated message (neg)

// ---------------- transform: new_emb = fb@W + b, s_b = new_emb@att2 ----------------
__global__ void transform_kernel(const float* __restrict__ fb,
                                 const float* __restrict__ W,
                                 const float* __restrict__ b,
                                 const float* __restrict__ att,   // [2*EMB]
                                 int n,
                                 float* __restrict__ emb_out,     // [n*PAD]
                                 float* __restrict__ sb_out) {
    __shared__ float Ws[EMB * EMB];
    __shared__ float bs[EMB];
    __shared__ float atts[EMB];
    for (int i = threadIdx.x; i < EMB * EMB; i += blockDim.x) Ws[i] = W[i];
    if (threadIdx.x < EMB) {
        bs[threadIdx.x]   = b[threadIdx.x];
        atts[threadIdx.x] = att[EMB + threadIdx.x];
    }
    __syncthreads();

    int row = blockIdx.x * blockDim.x + threadIdx.x;
    if (row >= n) return;

    float x[EMB];
#pragma unroll
    for (int k = 0; k < EMB; k++) x[k] = fb[row * EMB + k];

    float s = 0.f;
#pragma unroll
    for (int e = 0; e < EMB; e++) {
        float acc = bs[e];
#pragma unroll
        for (int k = 0; k < EMB; k++) acc += x[k] * Ws[k * EMB + e];
        emb_out[row * PAD + e] = acc;
        s += acc * atts[e];
    }
    sb_out[row] = s;
}

// ---------------- aggregate: warp per node, lane per neighbor ----------------
__global__ void aggregate_kernel(const float* __restrict__ fa,
                                 const float* __restrict__ att,   // [2*EMB]
                                 const int*   __restrict__ dst,   // [n*DEG]
                                 const float* __restrict__ emb,   // [*,PAD]
                                 const float* __restrict__ sb,
                                 int n,
                                 float* __restrict__ m_out) {     // [n*EMB]
    int warp = (blockIdx.x * blockDim.x + threadIdx.x) >> 5;
    int lane = threadIdx.x & 31;
    if (warp >= n) return;

    // s_a = dot(fa[warp], att[0:EMB])  (warp-cooperative)
    float p = fa[warp * EMB + lane] * att[lane];            // lanes 0..31 -> dims 0..31
    if (lane < EMB - 32)
        p += fa[warp * EMB + 32 + lane] * att[32 + lane];   // dims 32..34
#pragma unroll
    for (int o = 16; o; o >>= 1) p += __shfl_xor_sync(0xffffffffu, p, o);
    float sa = p;

    // per-lane neighbor: attention weight
    int   d  = dst[warp * DEG + lane];
    float s  = sa + sb[d];
    float el = s > 0.f ? s : 0.1f * expm1f(s);
    float w  = __expf(el);

    float den = w;
#pragma unroll
    for (int o = 16; o; o >>= 1) den += __shfl_xor_sync(0xffffffffu, den, o);

    // weighted sum of gathered rows: coalesced 35-float loads per neighbor
    float acc0 = 0.f, acc1 = 0.f;
#pragma unroll
    for (int j = 0; j < DEG; j++) {
        float wj = __shfl_sync(0xffffffffu, w, j);
        int   dj = __shfl_sync(0xffffffffu, d, j);
        const float* r = emb + (long)dj * PAD;
        acc0 += wj * r[lane];
        if (lane < 3) acc1 += wj * r[32 + lane];
    }

    float inv = 1.f / den;
    m_out[warp * EMB + lane] = acc0 * inv;
    if (lane < 3) m_out[warp * EMB + 32 + lane] = acc1 * inv;
}

// ---------------- update MLP: out = prelu(x@W1+b1)@W2+b2, x = [f, mp, mn] ----------------
__global__ void update_kernel(const float* __restrict__ f,
                              const float* __restrict__ mp,
                              const float* __restrict__ mn,
                              const float* __restrict__ W1,  // [105,70]
                              const float* __restrict__ b1,  // [70]
                              const float* __restrict__ alpha,
                              const float* __restrict__ W2,  // [70,35]
                              const float* __restrict__ b2,  // [35]
                              int n,
                              float* __restrict__ out) {
    __shared__ float W1s[105 * 72];   // padded to 72 for float4 LDS
    __shared__ float W2s[70 * 36];    // padded to 36
    __shared__ float b1s[72];
    __shared__ float b2s[36];
    for (int i = threadIdx.x; i < 105 * 72; i += blockDim.x) {
        int k = i / 72, e = i % 72;
        W1s[i] = (e < 70) ? W1[k * 70 + e] : 0.f;
    }
    for (int i = threadIdx.x; i < 70 * 36; i += blockDim.x) {
        int k = i / 36, e = i % 36;
        W2s[i] = (e < 35) ? W2[k * 35 + e] : 0.f;
    }
    if (threadIdx.x < 72) b1s[threadIdx.x] = (threadIdx.x < 70) ? b1[threadIdx.x] : 0.f;
    if (threadIdx.x < 36) b2s[threadIdx.x] = (threadIdx.x < 35) ? b2[threadIdx.x] : 0.f;
    __syncthreads();

    int row = blockIdx.x * blockDim.x + threadIdx.x;
    if (row >= n) return;
    float al = alpha[0];

    float h[72];
#pragma unroll
    for (int e = 0; e < 72; e++) h[e] = b1s[e];

    const float* srcs[3] = { f + row * EMB, mp + row * EMB, mn + row * EMB };
    for (int s3 = 0; s3 < 3; s3++) {
        const float* src = srcs[s3];
#pragma unroll
        for (int t = 0; t < EMB; t++) {
            float xk = src[t];
            int kk = s3 * EMB + t;
            const float4* wrow = (const float4*)(W1s + kk * 72);
#pragma unroll
            for (int e4 = 0; e4 < 18; e4++) {
                float4 w = wrow[e4];
                h[e4 * 4 + 0] += xk * w.x;
                h[e4 * 4 + 1] += xk * w.y;
                h[e4 * 4 + 2] += xk * w.z;
                h[e4 * 4 + 3] += xk * w.w;
            }
        }
    }

#pragma unroll
    for (int e = 0; e < 70; e++) h[e] = (h[e] > 0.f) ? h[e] : al * h[e];

    float o[36];
#pragma unroll
    for (int e = 0; e < 36; e++) o[e] = b2s[e];
#pragma unroll
    for (int k = 0; k < 70; k++) {
        float hk = h[k];
        const float4* wrow = (const float4*)(W2s + k * 36);
#pragma unroll
        for (int e4 = 0; e4 < 9; e4++) {
            float4 w = wrow[e4];
            o[e4 * 4 + 0] += hk * w.x;
            o[e4 * 4 + 1] += hk * w.y;
            o[e4 * 4 + 2] += hk * w.z;
            o[e4 * 4 + 3] += hk * w.w;
        }
    }

    float* op = out + (long)row * EMB;
#pragma unroll
    for (int e = 0; e < EMB; e++) op[e] = o[e];
}

// ---------------- launch ----------------
extern "C" void kernel_launch(void* const* d_in, const int* in_sizes, int n_in,
                              void* d_out, int out_size) {
    const float* fa     = (const float*)d_in[0];
    const float* fb     = (const float*)d_in[1];
    const int*   dab_p  = (const int*)  d_in[2];
    const int*   dab_n  = (const int*)  d_in[3];
    const int*   dba_p  = (const int*)  d_in[4];
    const int*   dba_n  = (const int*)  d_in[5];
    const float* W_abp  = (const float*)d_in[6];
    const float* b_abp  = (const float*)d_in[7];
    const float* a_abp  = (const float*)d_in[8];
    const float* W_abn  = (const float*)d_in[9];
    const float* b_abn  = (const float*)d_in[10];
    const float* a_abn  = (const float*)d_in[11];
    const float* W_bap  = (const float*)d_in[12];
    const float* b_bap  = (const float*)d_in[13];
    const float* a_bap  = (const float*)d_in[14];
    const float* W_ban  = (const float*)d_in[15];
    const float* b_ban  = (const float*)d_in[16];
    const float* a_ban  = (const float*)d_in[17];
    const float* W1     = (const float*)d_in[18];
    const float* b1     = (const float*)d_in[19];
    const float* alpha  = (const float*)d_in[20];
    const float* W2     = (const float*)d_in[21];
    const float* b2     = (const float*)d_in[22];
    float* out = (float*)d_out;

    float *emb, *sb, *m0, *m1;
    cudaGetSymbolAddress((void**)&emb, g_emb);
    cudaGetSymbolAddress((void**)&sb,  g_sb);
    cudaGetSymbolAddress((void**)&m0,  g_m0);
    cudaGetSymbolAddress((void**)&m1,  g_m1);

    const int n = N_NODES;
    dim3 tb_t(128);  dim3 gr_t((n + 127) / 128);
    dim3 tb_a(256);  dim3 gr_a((n * 32 + 255) / 256);
    dim3 tb_u(128);  dim3 gr_u((n + 127) / 128);

    // ---- side A: aggregate from B ----
    transform_kernel<<<gr_t, tb_t>>>(fb, W_abp, b_abp, a_abp, n, emb, sb);
    aggregate_kernel<<<gr_a, tb_a>>>(fa, a_abp, dab_p, emb, sb, n, m0);
    transform_kernel<<<gr_t, tb_t>>>(fb, W_abn, b_abn, a_abn, n, emb, sb);
    aggregate_kernel<<<gr_a, tb_a>>>(fa, a_abn, dab_n, emb, sb, n, m1);
    update_kernel<<<gr_u, tb_u>>>(fa, m0, m1, W1, b1, alpha, W2, b2, n, out);

    // ---- side B: aggregate from A ----
    transform_kernel<<<gr_t, tb_t>>>(fa, W_bap, b_bap, a_bap, n, emb, sb);
    aggregate_kernel<<<gr_a, tb_a>>>(fb, a_bap, dba_p, emb, sb, n, m0);
    transform_kernel<<<gr_t, tb_t>>>(fa, W_ban, b_ban, a_ban, n, emb, sb);
    aggregate_kernel<<<gr_a, tb_a>>>(fb, a_ban, dba_n, emb, sb, n, m1);
    update_kernel<<<gr_u, tb_u>>>(fb, m0, m1, W1, b1, alpha, W2, b2, n, out + (long)n * EMB);

    (void)in_sizes; (void)n_in; (void)out_size;
}